// round 4
// baseline (speedup 1.0000x reference)
#include <cuda_runtime.h>

#define VSZ 50257
#define Dk  50
#define TT  1024
#define BSZ 1024
#define BB  8
#define NT  672

// Precomputed emb @ kx1 + b1[0] table: [V, 96] fp32 (L2-resident, 19.3MB)
__device__ float g_proj1[VSZ * 96];

typedef unsigned long long u64;

__device__ __forceinline__ u64 pk2(float a, float b) {
    u64 r; asm("mov.b64 %0, {%1, %2};" : "=l"(r) : "f"(a), "f"(b)); return r;
}
__device__ __forceinline__ void upk2(u64 v, float& a, float& b) {
    asm("mov.b64 {%0, %1}, %2;" : "=f"(a), "=f"(b) : "l"(v));
}
__device__ __forceinline__ u64 ffma2(u64 a, u64 b, u64 c) {
    u64 d; asm("fma.rn.f32x2 %0, %1, %2, %3;" : "=l"(d) : "l"(a), "l"(b), "l"(c)); return d;
}
__device__ __forceinline__ u64 fadd2(u64 a, u64 b) {
    u64 d; asm("add.rn.f32x2 %0, %1, %2;" : "=l"(d) : "l"(a), "l"(b)); return d;
}
__device__ __forceinline__ float sgm(float x) { return 1.0f / (1.0f + __expf(-x)); }
__device__ __forceinline__ float tnh(float x) { return 2.0f * sgm(2.0f * x) - 1.0f; }

__device__ __forceinline__ u64 gru_gate(u64 xz, u64 hz, u64 xr, u64 hr,
                                        u64 xh, u64 hh, u64 hold) {
    float az0, az1, ar0, ar1, xh0, xh1, hh0, hh1, g0, g1;
    upk2(fadd2(xz, hz), az0, az1);
    upk2(fadd2(xr, hr), ar0, ar1);
    upk2(xh, xh0, xh1); upk2(hh, hh0, hh1); upk2(hold, g0, g1);
    float z0 = sgm(az0), z1 = sgm(az1);
    float r0 = sgm(ar0), r1 = sgm(ar1);
    float c0 = tnh(xh0 + r0 * hh0);
    float c1 = tnh(xh1 + r1 * hh1);
    return pk2(z0 * g0 + (1.0f - z0) * c0, z1 * g1 + (1.0f - z1) * c1);
}

// ---------------------------------------------------------------------------
__global__ void proj_kernel(const float* __restrict__ emb,
                            const float* __restrict__ kx1,
                            const float* __restrict__ b1) {
    __shared__ float kxs[Dk * 96];
    __shared__ float embs[16 * Dk];
    int tid = threadIdx.x;
    for (int i = tid; i < Dk * 96; i += 256) kxs[i] = kx1[i];
    int vbase = blockIdx.x * 16;
    for (int i = tid; i < 16 * Dk; i += 256) {
        int r = i / Dk, d = i - r * Dk;
        int v = vbase + r;
        embs[i] = (v < VSZ) ? emb[v * Dk + d] : 0.0f;
    }
    __syncthreads();
    for (int i = tid; i < 16 * 96; i += 256) {
        int r = i / 96, j = i - r * 96;
        int v = vbase + r;
        if (v >= VSZ) continue;
        float acc = b1[j];
        #pragma unroll
        for (int d = 0; d < Dk; d++)
            acc = fmaf(embs[r * Dk + d], kxs[d * 96 + j], acc);
        g_proj1[v * 96 + j] = acc;
    }
}

// ---------------------------------------------------------------------------
// Dynamic shared layout (bytes). States stored as duplicated (h,h) u64 pairs.
// Result buffers padded to 10 floats per column row.
// ---------------------------------------------------------------------------
#define OFF_H1D  0        // [32][8] u64   2048
#define OFF_H2D  2048     // [64][8] u64   4096
#define OFF_P3A  6144     // [192][10] f32 7680  (hm2 partial, u<32)
#define OFF_P3B  13824    // [192][10] f32 7680  (hm2 partial, u>=32)
#define OFF_P2A  21504    // [192][10] f32 7680  (xg2 partial, u<16)
#define OFF_P2B  29184    // [192][10] f32 7680  (xg2 partial, u>=16)
#define OFF_P1A  36864    // [96][10]  f32 3840  (hm1 partial, u<16)
#define OFF_P1B  40704    // [96][10]  f32 3840  (hm1 partial, u>=16)
#define OFF_XG1  44544    // [2][96][10] f32 7680
#define OFF_TOK  52224    // [8][32] int 1024
#define OFF_AGS  6144     // epilogue alias [8][256] f32 (8192)
#define OFF_GWS  16384    // epilogue alias [8][128] f32 (4096)
#define SMEM_SZ  53248

__global__ void __launch_bounds__(NT, 1) rnn_kernel(
    const int*   __restrict__ tokens,
    const float* __restrict__ kh1,   // [32][96]
    const float* __restrict__ b1,    // [2][96]
    const float* __restrict__ kx2,   // [32][192]
    const float* __restrict__ kh2,   // [64][192]
    const float* __restrict__ b2,    // [2][192]
    const float* __restrict__ wg,    // [64][256]
    const float* __restrict__ bg,    // [256]
    const float* __restrict__ wd,    // [128]
    const float* __restrict__ bd,    // [1]
    float*       __restrict__ out)
{
    extern __shared__ char sbuf[];
    u64*   h1d  = (u64*)(sbuf + OFF_H1D);
    u64*   h2d  = (u64*)(sbuf + OFF_H2D);
    float* p3a  = (float*)(sbuf + OFF_P3A);
    float* p3b  = (float*)(sbuf + OFF_P3B);
    float* p2a  = (float*)(sbuf + OFF_P2A);
    float* p2b  = (float*)(sbuf + OFF_P2B);
    float* p1a  = (float*)(sbuf + OFF_P1A);
    float* p1b  = (float*)(sbuf + OFF_P1B);
    float* xg1f = (float*)(sbuf + OFF_XG1);
    int*   tok  = (int*)(sbuf + OFF_TOK);

    const int tid = threadIdx.x;
    const int b0  = blockIdx.x * BB;

    // ---------------- role decode + weights into registers ----------------
    // G3 (hm2): tid in [0,384):   col-pair c3, batch-half hf3, u-half uh3 (32u)
    // G2 (xg2): tid in [384,576): col-pair c2, u-half uh2 (16u), 8 batches
    // G1 (hm1): tid in [576,672): col-pair c1, u-half uh1 (16u), 8 batches
    u64 wq[32];
    u64 bq = 0ull;
    int c3 = 0, hf3 = 0, uh3 = 0, c2 = 0, uh2 = 0, c1 = 0, uh1 = 0;
    if (tid < 384) {
        c3 = tid % 96; hf3 = (tid / 96) & 1; uh3 = tid / 192;
        #pragma unroll
        for (int uu = 0; uu < 32; uu++) {
            float2 w = *(const float2*)&kh2[(uh3 * 32 + uu) * 192 + 2 * c3];
            wq[uu] = pk2(w.x, w.y);
        }
        if (uh3 == 0) {
            float2 bb = *(const float2*)&b2[192 + 2 * c3];
            bq = pk2(bb.x, bb.y);
        }
    } else if (tid < 576) {
        int t = tid - 384; c2 = t % 96; uh2 = t / 96;
        #pragma unroll
        for (int uu = 0; uu < 16; uu++) {
            float2 w = *(const float2*)&kx2[(uh2 * 16 + uu) * 192 + 2 * c2];
            wq[uu] = pk2(w.x, w.y);
        }
        if (uh2 == 0) {
            float2 bb = *(const float2*)&b2[2 * c2];
            bq = pk2(bb.x, bb.y);
        }
    } else {
        int t = tid - 576; c1 = t % 48; uh1 = t / 48;
        #pragma unroll
        for (int uu = 0; uu < 16; uu++) {
            float2 w = *(const float2*)&kh1[(uh1 * 16 + uu) * 96 + 2 * c1];
            wq[uu] = pk2(w.x, w.y);
        }
        if (uh1 == 0) {
            float2 bb = *(const float2*)&b1[96 + 2 * c1];
            bq = pk2(bb.x, bb.y);
        }
    }

    // ---------------- init: zero states, token chunk 0 ----------------
    for (int i = tid; i < 768; i += NT) ((u64*)sbuf)[i] = 0ull;  // h1d+h2d
    if (tid < 256) {
        int b = tid >> 5, o = tid & 31;
        tok[b * 32 + o] = tokens[(b0 + b) * TT + o];
    }
    __syncthreads();
    for (int i = tid; i < 768; i += NT) {
        int b = i / 96, j = i - 96 * (i / 96);
        xg1f[0 * 960 + j * 10 + b] = __ldg(&g_proj1[tok[b * 32 + 0] * 96 + j]);
        xg1f[1 * 960 + j * 10 + b] = __ldg(&g_proj1[tok[b * 32 + 1] * 96 + j]);
    }
    __syncthreads();
    // GRU1 step 0 (h=0)
    if (tid < 128) {
        int u = tid & 31, bo = (tid >> 5) * 2;
        float2 xz = *(const float2*)&xg1f[(u)      * 10 + bo];
        float2 xr = *(const float2*)&xg1f[(32 + u) * 10 + bo];
        float2 xh = *(const float2*)&xg1f[(64 + u) * 10 + bo];
        float bz = b1[96 + u], br = b1[128 + u], bh = b1[160 + u];
        u64 hn = gru_gate(pk2(xz.x, xz.y), pk2(bz, bz),
                          pk2(xr.x, xr.y), pk2(br, br),
                          pk2(xh.x, xh.y), pk2(bh, bh), 0ull);
        float n0, n1; upk2(hn, n0, n1);
        *(ulonglong2*)&h1d[u * 8 + bo] = make_ulonglong2(pk2(n0, n0), pk2(n1, n1));
    }
    __syncthreads();

    // gather mapping: 768 loads over 672 threads (+96 extra on tid<96)
    const int gb0 = tid / 96, gj0 = tid % 96;   // batches 0..6
    float gv0 = 0.0f, gv1 = 0.0f;               // gv1: batch 7, col tid (tid<96)

    #pragma unroll 1
    for (int k = 0; k < TT; k++) {
        // ================= Phase A: gathers + 3 GEMMs =================
        if (k < TT - 2) {
            int slot = (k + 2) & 31;
            gv0 = __ldg(&g_proj1[tok[gb0 * 32 + slot] * 96 + gj0]);
            if (tid < 96)
                gv1 = __ldg(&g_proj1[tok[7 * 32 + slot] * 96 + tid]);
        }
        if (tid < 384) {
            // G3: hm2 partial (2 cols x 4 batches x 32u)
            u64 a0 = bq, a1 = bq, a2 = bq, a3 = bq;
            const char* hb = (const char*)h2d + uh3 * 32 * 64 + hf3 * 32;
            #pragma unroll
            for (int uu = 0; uu < 32; uu++) {
                ulonglong2 hA = *(const ulonglong2*)(hb + uu * 64);
                ulonglong2 hB = *(const ulonglong2*)(hb + uu * 64 + 16);
                a0 = ffma2(wq[uu], hA.x, a0); a1 = ffma2(wq[uu], hA.y, a1);
                a2 = ffma2(wq[uu], hB.x, a2); a3 = ffma2(wq[uu], hB.y, a3);
            }
            float* o0 = (uh3 ? p3b : p3a) + (2 * c3) * 10 + 4 * hf3;
            float f0, f1;
            upk2(a0, f0, f1); o0[0] = f0; o0[10] = f1;
            upk2(a1, f0, f1); o0[1] = f0; o0[11] = f1;
            upk2(a2, f0, f1); o0[2] = f0; o0[12] = f1;
            upk2(a3, f0, f1); o0[3] = f0; o0[13] = f1;
        } else if (tid < 576) {
            // G2: xg2 partial (2 cols x 8 batches x 16u)
            u64 a[8];
            #pragma unroll
            for (int p = 0; p < 8; p++) a[p] = bq;
            const u64* hbase = h1d + uh2 * 16 * 8;
            #pragma unroll
            for (int uu = 0; uu < 16; uu++) {
                const ulonglong2* hp = (const ulonglong2*)&hbase[uu * 8];
                ulonglong2 hA = hp[0], hB = hp[1], hC = hp[2], hD = hp[3];
                a[0] = ffma2(wq[uu], hA.x, a[0]); a[1] = ffma2(wq[uu], hA.y, a[1]);
                a[2] = ffma2(wq[uu], hB.x, a[2]); a[3] = ffma2(wq[uu], hB.y, a[3]);
                a[4] = ffma2(wq[uu], hC.x, a[4]); a[5] = ffma2(wq[uu], hC.y, a[5]);
                a[6] = ffma2(wq[uu], hD.x, a[6]); a[7] = ffma2(wq[uu], hD.y, a[7]);
            }
            float* o0 = (uh2 ? p2b : p2a) + (2 * c2) * 10;
            #pragma unroll
            for (int p = 0; p < 8; p++) {
                float f0, f1; upk2(a[p], f0, f1);
                o0[p] = f0; o0[10 + p] = f1;
            }
        } else {
            // G1: hm1(t+1) partial (2 cols x 8 batches x 16u)
            u64 a[8];
            #pragma unroll
            for (int p = 0; p < 8; p++) a[p] = bq;
            const u64* hbase = h1d + uh1 * 16 * 8;
            #pragma unroll
            for (int uu = 0; uu < 16; uu++) {
                const ulonglong2* hp = (const ulonglong2*)&hbase[uu * 8];
                ulonglong2 hA = hp[0], hB = hp[1], hC = hp[2], hD = hp[3];
                a[0] = ffma2(wq[uu], hA.x, a[0]); a[1] = ffma2(wq[uu], hA.y, a[1]);
                a[2] = ffma2(wq[uu], hB.x, a[2]); a[3] = ffma2(wq[uu], hB.y, a[3]);
                a[4] = ffma2(wq[uu], hC.x, a[4]); a[5] = ffma2(wq[uu], hC.y, a[5]);
                a[6] = ffma2(wq[uu], hD.x, a[6]); a[7] = ffma2(wq[uu], hD.y, a[7]);
            }
            float* o0 = (uh1 ? p1b : p1a) + (2 * c1) * 10;
            #pragma unroll
            for (int p = 0; p < 8; p++) {
                float f0, f1; upk2(a[p], f0, f1);
                o0[p] = f0; o0[10 + p] = f1;
            }
        }
        __syncthreads();

        // ================= Phase B: gates + gather stores =================
        if (k < TT - 2) {
            int buf = (k + 2) & 1;
            float* xb = xg1f + buf * 960;
            xb[gj0 * 10 + gb0] = gv0;
            if (tid < 96) xb[tid * 10 + 7] = gv1;
        }
        if (tid < 128) {
            // GRU2 gates, step k
            int u = tid & 63, gh = tid >> 6;
            #pragma unroll
            for (int pp = 0; pp < 2; pp++) {
                int bo = 2 * (2 * gh + pp);
                #define CMB(pa, pb, idx) ({                                  \
                    float2 _a = *(const float2*)&pa[(idx) * 10 + bo];        \
                    float2 _b = *(const float2*)&pb[(idx) * 10 + bo];        \
                    fadd2(pk2(_a.x, _a.y), pk2(_b.x, _b.y)); })
                u64 xz = CMB(p2a, p2b, u);
                u64 xr = CMB(p2a, p2b, 64 + u);
                u64 xh = CMB(p2a, p2b, 128 + u);
                u64 hz = CMB(p3a, p3b, u);
                u64 hr = CMB(p3a, p3b, 64 + u);
                u64 hh = CMB(p3a, p3b, 128 + u);
                float4 hv = *(const float4*)&h2d[u * 8 + bo];
                u64 hn = gru_gate(xz, hz, xr, hr, xh, hh, pk2(hv.x, hv.z));
                float n0, n1; upk2(hn, n0, n1);
                *(ulonglong2*)&h2d[u * 8 + bo] =
                    make_ulonglong2(pk2(n0, n0), pk2(n1, n1));
            }
        } else if (tid < 256 && k < TT - 1) {
            // GRU1 gates, step k+1
            int t2 = tid - 128;
            int u = t2 & 31, bo = 2 * (t2 >> 5);
            const float* xb = xg1f + ((k + 1) & 1) * 960;
            float2 xzf = *(const float2*)&xb[(u)      * 10 + bo];
            float2 xrf = *(const float2*)&xb[(32 + u) * 10 + bo];
            float2 xhf = *(const float2*)&xb[(64 + u) * 10 + bo];
            u64 hz = CMB(p1a, p1b, u);
            u64 hr = CMB(p1a, p1b, 32 + u);
            u64 hh = CMB(p1a, p1b, 64 + u);
            float4 hv = *(const float4*)&h1d[u * 8 + bo];
            u64 hn = gru_gate(pk2(xzf.x, xzf.y), hz,
                              pk2(xrf.x, xrf.y), hr,
                              pk2(xhf.x, xhf.y), hh, pk2(hv.x, hv.z));
            float n0, n1; upk2(hn, n0, n1);
            *(ulonglong2*)&h1d[u * 8 + bo] =
                make_ulonglong2(pk2(n0, n0), pk2(n1, n1));
        }
        if (((k + 3) & 31) == 0 && (k + 3) < TT && tid < 256) {
            int b = tid >> 5, o = tid & 31;
            tok[b * 32 + o] = tokens[(b0 + b) * TT + (k + 3) + o];
        }
        __syncthreads();
    }

    // ================= Epilogue: GLU + dense + sigmoid =================
    float* ags = (float*)(sbuf + OFF_AGS);   // [8][256]
    float* gws = (float*)(sbuf + OFF_GWS);   // [8][128]
    if (tid < 256) {
        int c = tid;
        float bgv = bg[c];
        u64 acc0 = pk2(bgv, bgv), acc1 = acc0, acc2 = acc0, acc3 = acc0;
        #pragma unroll
        for (int u = 0; u < 64; u++) {
            const float4* hp = (const float4*)&h2d[u * 8];
            float4 v01 = hp[0], v23 = hp[1], v45 = hp[2], v67 = hp[3];
            float wv = __ldg(&wg[u * 256 + c]);
            u64 w = pk2(wv, wv);
            acc0 = ffma2(w, pk2(v01.x, v01.z), acc0);
            acc1 = ffma2(w, pk2(v23.x, v23.z), acc1);
            acc2 = ffma2(w, pk2(v45.x, v45.z), acc2);
            acc3 = ffma2(w, pk2(v67.x, v67.z), acc3);
        }
        float f0, f1;
        upk2(acc0, f0, f1); ags[0 * 256 + c] = f0; ags[1 * 256 + c] = f1;
        upk2(acc1, f0, f1); ags[2 * 256 + c] = f0; ags[3 * 256 + c] = f1;
        upk2(acc2, f0, f1); ags[4 * 256 + c] = f0; ags[5 * 256 + c] = f1;
        upk2(acc3, f0, f1); ags[6 * 256 + c] = f0; ags[7 * 256 + c] = f1;
    }
    __syncthreads();
    for (int i = tid; i < 1024; i += NT) {
        int b = i >> 7, kk = i & 127;
        float g = ags[b * 256 + kk] * sgm(ags[b * 256 + 128 + kk]);
        gws[b * 128 + kk] = g * __ldg(&wd[kk]);
    }
    __syncthreads();
    if (tid < BB) {
        float s = bd[0];
        #pragma unroll
        for (int kk = 0; kk < 128; kk++) s += gws[tid * 128 + kk];
        out[b0 + tid] = sgm(s);
    }
}

// ---------------------------------------------------------------------------
extern "C" void kernel_launch(void* const* d_in, const int* in_sizes, int n_in,
                              void* d_out, int out_size) {
    (void)in_sizes; (void)n_in; (void)out_size;
    const int*   tokens = (const int*)  d_in[0];
    const float* emb    = (const float*)d_in[1];
    const float* kx1    = (const float*)d_in[2];
    const float* kh1    = (const float*)d_in[3];
    const float* b1     = (const float*)d_in[4];
    const float* kx2    = (const float*)d_in[5];
    const float* kh2    = (const float*)d_in[6];
    const float* b2     = (const float*)d_in[7];
    const float* wg     = (const float*)d_in[8];
    const float* bg     = (const float*)d_in[9];
    const float* wd     = (const float*)d_in[10];
    const float* bd     = (const float*)d_in[11];

    static int smem_set = 0;
    if (!smem_set) {
        cudaFuncSetAttribute(rnn_kernel,
                             cudaFuncAttributeMaxDynamicSharedMemorySize, SMEM_SZ);
        smem_set = 1;
    }

    proj_kernel<<<(VSZ + 15) / 16, 256>>>(emb, kx1, b1);
    rnn_kernel<<<BSZ / BB, NT, SMEM_SZ>>>(tokens, kh1, b1, kx2, kh2, b2,
                                          wg, bg, wd, bd, (float*)d_out);
}

// round 5
// speedup vs baseline: 1.1018x; 1.1018x over previous
#include <cuda_runtime.h>

#define VSZ 50257
#define Dk  50
#define TT  1024
#define BSZ 1024
#define BB  8
#define NT  672

// Precomputed emb @ kx1 + b1[0] table: [V, 96] fp32 (L2-resident, 19.3MB)
__device__ float g_proj1[VSZ * 96];

typedef unsigned long long u64;

__device__ __forceinline__ u64 pk2(float a, float b) {
    u64 r; asm("mov.b64 %0, {%1, %2};" : "=l"(r) : "f"(a), "f"(b)); return r;
}
__device__ __forceinline__ void upk2(u64 v, float& a, float& b) {
    asm("mov.b64 {%0, %1}, %2;" : "=f"(a), "=f"(b) : "l"(v));
}
__device__ __forceinline__ u64 ffma2(u64 a, u64 b, u64 c) {
    u64 d; asm("fma.rn.f32x2 %0, %1, %2, %3;" : "=l"(d) : "l"(a), "l"(b), "l"(c)); return d;
}
__device__ __forceinline__ float sgm(float x) { return 1.0f / (1.0f + __expf(-x)); }
__device__ __forceinline__ float tnh(float x) { return 2.0f * sgm(2.0f * x) - 1.0f; }

// scalar GRU update
__device__ __forceinline__ float gru1s(float xz, float hz, float xr, float hr,
                                       float xh, float hh, float hold) {
    float z = sgm(xz + hz);
    float r = sgm(xr + hr);
    float c = tnh(xh + r * hh);
    return z * hold + (1.0f - z) * c;
}

// ---------------------------------------------------------------------------
__global__ void proj_kernel(const float* __restrict__ emb,
                            const float* __restrict__ kx1,
                            const float* __restrict__ b1) {
    __shared__ float kxs[Dk * 96];
    __shared__ float embs[16 * Dk];
    int tid = threadIdx.x;
    for (int i = tid; i < Dk * 96; i += 256) kxs[i] = kx1[i];
    int vbase = blockIdx.x * 16;
    for (int i = tid; i < 16 * Dk; i += 256) {
        int r = i / Dk, d = i - r * Dk;
        int v = vbase + r;
        embs[i] = (v < VSZ) ? emb[v * Dk + d] : 0.0f;
    }
    __syncthreads();
    for (int i = tid; i < 16 * 96; i += 256) {
        int r = i / 96, j = i - r * 96;
        int v = vbase + r;
        if (v >= VSZ) continue;
        float acc = b1[j];
        #pragma unroll
        for (int d = 0; d < Dk; d++)
            acc = fmaf(embs[r * Dk + d], kxs[d * 96 + j], acc);
        g_proj1[v * 96 + j] = acc;
    }
}

// ---------------------------------------------------------------------------
// Shared layout (bytes). States stored as duplicated (h,h) u64 pairs.
// Partial result buffers: 12 floats per column (16B-aligned float4 stores).
// ---------------------------------------------------------------------------
#define OFF_H1D  0        // [32][8] u64  2048
#define OFF_H2D  2048     // [64][8] u64  4096
#define OFF_P3   6144     // 4 x [192][12] f32 = 4 x 9216
#define OFF_P2   43008    // 2 x [192][12] f32 = 2 x 9216
#define OFF_P1   61440    // 2 x [96][12]  f32 = 2 x 4608
#define OFF_XG1  70656    // 2 x [96][12]  f32 = 9216
#define OFF_TOK  79872    // [8][32] int 1024
#define OFF_BIA3 80896    // 192 f32
#define OFF_BIA2 81664    // 192 f32
#define OFF_BIA1 82432    // 96 f32
#define SMEM_SZ  82816
#define OFF_AGS  6144     // epilogue alias [8][256] f32 (8192)
#define OFF_GWS  14336    // epilogue alias [8][128] f32 (4096)

#define F2(ptr, off) (*(const float2*)&(ptr)[off])

__global__ void __launch_bounds__(NT, 1) rnn_kernel(
    const int*   __restrict__ tokens,
    const float* __restrict__ kh1,   // [32][96]
    const float* __restrict__ b1,    // [2][96]
    const float* __restrict__ kx2,   // [32][192]
    const float* __restrict__ kh2,   // [64][192]
    const float* __restrict__ b2,    // [2][192]
    const float* __restrict__ wg,    // [64][256]
    const float* __restrict__ bg,    // [256]
    const float* __restrict__ wd,    // [128]
    const float* __restrict__ bd,    // [1]
    float*       __restrict__ out)
{
    extern __shared__ char sbuf[];
    u64*   h1d  = (u64*)(sbuf + OFF_H1D);
    u64*   h2d  = (u64*)(sbuf + OFF_H2D);
    float* P3   = (float*)(sbuf + OFF_P3);    // +2304 floats per buf
    float* P2   = (float*)(sbuf + OFF_P2);
    float* P1   = (float*)(sbuf + OFF_P1);    // +1152 floats per buf
    float* xg1  = (float*)(sbuf + OFF_XG1);   // 2 bufs of 1152 floats
    int*   tok  = (int*)(sbuf + OFF_TOK);
    float* bia3 = (float*)(sbuf + OFF_BIA3);
    float* bia2 = (float*)(sbuf + OFF_BIA2);
    float* bia1 = (float*)(sbuf + OFF_BIA1);

    const int tid = threadIdx.x;
    const int b0  = blockIdx.x * BB;

    // ------------- role decode + weights into registers -------------
    // G3 (hm2): tid [0,384):   uh=tid/96 (16u), r=tid%96: bh=r/48, q=r%48 (4 cols)
    // G2 (xg2): tid [384,576): uh=(t)/96 (16u), bh, q (48 quads)
    // G1 (hm1): tid [576,672): uh=(t)/48 (16u), bh=(t%48)/24, q=t%24 (24 quads)
    u64 wq[32];
    int uh = 0, bh = 0, q = 0;
    const float* hbase;            // state read base (byte addr via char*)
    float* obase;                  // partial output base
    const float* biap = 0;         // bias (uh==0 only)
    if (tid < 384) {
        uh = tid / 96; int r = tid % 96; bh = r / 48; q = r % 48;
        #pragma unroll
        for (int uu = 0; uu < 16; uu++) {
            float4 w = *(const float4*)&kh2[(uh * 16 + uu) * 192 + 4 * q];
            wq[2 * uu] = pk2(w.x, w.y); wq[2 * uu + 1] = pk2(w.z, w.w);
        }
        hbase = (const float*)((const char*)h2d + uh * 16 * 64 + bh * 32);
        obase = P3 + uh * 2304 + (4 * q) * 12 + 4 * bh;
        if (uh == 0) biap = bia3 + 4 * q;
    } else if (tid < 576) {
        int t = tid - 384;
        uh = t / 96; int r = t % 96; bh = r / 48; q = r % 48;
        #pragma unroll
        for (int uu = 0; uu < 16; uu++) {
            float4 w = *(const float4*)&kx2[(uh * 16 + uu) * 192 + 4 * q];
            wq[2 * uu] = pk2(w.x, w.y); wq[2 * uu + 1] = pk2(w.z, w.w);
        }
        hbase = (const float*)((const char*)h1d + uh * 16 * 64 + bh * 32);
        obase = P2 + uh * 2304 + (4 * q) * 12 + 4 * bh;
        if (uh == 0) biap = bia2 + 4 * q;
    } else {
        int t = tid - 576;
        uh = t / 48; int r = t % 48; bh = r / 24; q = r % 24;
        #pragma unroll
        for (int uu = 0; uu < 16; uu++) {
            float4 w = *(const float4*)&kh1[(uh * 16 + uu) * 96 + 4 * q];
            wq[2 * uu] = pk2(w.x, w.y); wq[2 * uu + 1] = pk2(w.z, w.w);
        }
        hbase = (const float*)((const char*)h1d + uh * 16 * 64 + bh * 32);
        obase = P1 + uh * 1152 + (4 * q) * 12 + 4 * bh;
        if (uh == 0) biap = bia1 + 4 * q;
    }

    // gather mapping for tid >= 384 (288 threads cover 768 gathers)
    int gi = tid - 384;
    int gb0i = 0, gj0 = 0, gb1i = 0, gj1 = 0, gb2i = 0, gj2 = 0;
    if (gi >= 0) {
        gb0i = gi / 96;          gj0 = gi % 96;
        gb1i = (gi + 288) / 96;  gj1 = (gi + 288) % 96;
        if (gi < 192) { gb2i = (gi + 576) / 96; gj2 = (gi + 576) % 96; }
    }

    // ------------- init: biases, zero states, token chunk 0 -------------
    if (tid < 192) { bia3[tid] = b2[192 + tid]; bia2[tid] = b2[tid]; }
    if (tid >= 192 && tid < 288) bia1[tid - 192] = b1[96 + (tid - 192)];
    for (int i = tid; i < 768; i += NT) ((u64*)sbuf)[i] = 0ull;   // h1d + h2d
    if (tid >= 384 && tid < 640) {
        int t = tid - 384, b = t >> 5, o = t & 31;
        tok[b * 32 + o] = tokens[(b0 + b) * TT + o];
    }
    __syncthreads();
    for (int i = tid; i < 768; i += NT) {
        int b = i / 96, j = i - 96 * (i / 96);
        xg1[0 * 1152 + j * 12 + b] = __ldg(&g_proj1[tok[b * 32 + 0] * 96 + j]);
        xg1[1 * 1152 + j * 12 + b] = __ldg(&g_proj1[tok[b * 32 + 1] * 96 + j]);
    }
    __syncthreads();
    // GRU1 step 0 (h=0): recurrent term is just bias
    if (tid < 128) {
        int u = tid & 31, bo = 2 * (tid >> 5);
        float2 xz = F2(xg1, (u)      * 12 + bo);
        float2 xr = F2(xg1, (32 + u) * 12 + bo);
        float2 xh = F2(xg1, (64 + u) * 12 + bo);
        float bz = bia1[u], br = bia1[32 + u], bhv = bia1[64 + u];
        float n0 = gru1s(xz.x, bz, xr.x, br, xh.x, bhv, 0.0f);
        float n1 = gru1s(xz.y, bz, xr.y, br, xh.y, bhv, 0.0f);
        *(float4*)&h1d[u * 8 + bo] = make_float4(n0, n0, n1, n1);
    }
    __syncthreads();

    float gv0 = 0.0f, gv1 = 0.0f, gv2 = 0.0f;

    #pragma unroll 1
    for (int k = 0; k < TT; k++) {
        // ================= Phase A: gathers + 3 GEMMs =================
        if (gi >= 0 && k < TT - 2) {
            int slot = (k + 2) & 31;
            gv0 = __ldg(&g_proj1[tok[gb0i * 32 + slot] * 96 + gj0]);
            gv1 = __ldg(&g_proj1[tok[gb1i * 32 + slot] * 96 + gj1]);
            if (gi < 192)
                gv2 = __ldg(&g_proj1[tok[gb2i * 32 + slot] * 96 + gj2]);
        }
        {
            u64 a0[4], a1[4];
            u64 bq0 = 0ull, bq1 = 0ull;
            if (biap) {
                float4 bb = *(const float4*)biap;
                bq0 = pk2(bb.x, bb.y); bq1 = pk2(bb.z, bb.w);
            }
            #pragma unroll
            for (int p = 0; p < 4; p++) { a0[p] = bq0; a1[p] = bq1; }
            #pragma unroll
            for (int uu = 0; uu < 16; uu++) {
                ulonglong2 hA = *(const ulonglong2*)((const char*)hbase + uu * 64);
                ulonglong2 hB = *(const ulonglong2*)((const char*)hbase + uu * 64 + 16);
                u64 w0 = wq[2 * uu], w1 = wq[2 * uu + 1];
                a0[0] = ffma2(w0, hA.x, a0[0]); a0[1] = ffma2(w0, hA.y, a0[1]);
                a0[2] = ffma2(w0, hB.x, a0[2]); a0[3] = ffma2(w0, hB.y, a0[3]);
                a1[0] = ffma2(w1, hA.x, a1[0]); a1[1] = ffma2(w1, hA.y, a1[1]);
                a1[2] = ffma2(w1, hB.x, a1[2]); a1[3] = ffma2(w1, hB.y, a1[3]);
            }
            // transpose: lanes are columns -> store per-column float4 of batches
            float c00, c10, c01, c11, c02, c12, c03, c13;
            upk2(a0[0], c00, c10); upk2(a0[1], c01, c11);
            upk2(a0[2], c02, c12); upk2(a0[3], c03, c13);
            *(float4*)&obase[0]  = make_float4(c00, c01, c02, c03);
            *(float4*)&obase[12] = make_float4(c10, c11, c12, c13);
            upk2(a1[0], c00, c10); upk2(a1[1], c01, c11);
            upk2(a1[2], c02, c12); upk2(a1[3], c03, c13);
            *(float4*)&obase[24] = make_float4(c00, c01, c02, c03);
            *(float4*)&obase[36] = make_float4(c10, c11, c12, c13);
        }
        __syncthreads();

        // ================= Phase B: gates (384 thr) + stores =================
        if (tid < 256) {
            // GRU2 gates, step k: one batch pair each
            int u = tid & 63, bo = 2 * (tid >> 6);
            int cz = u * 12 + bo, cr = (64 + u) * 12 + bo, ch = (128 + u) * 12 + bo;
            float2 x0, x1, s0, s1, s2, s3;
            x0 = F2(P2, cz); x1 = F2(P2 + 2304, cz);
            float xz0 = x0.x + x1.x, xz1 = x0.y + x1.y;
            x0 = F2(P2, cr); x1 = F2(P2 + 2304, cr);
            float xr0 = x0.x + x1.x, xr1 = x0.y + x1.y;
            x0 = F2(P2, ch); x1 = F2(P2 + 2304, ch);
            float xh0 = x0.x + x1.x, xh1 = x0.y + x1.y;
            s0 = F2(P3, cz); s1 = F2(P3 + 2304, cz); s2 = F2(P3 + 4608, cz); s3 = F2(P3 + 6912, cz);
            float hz0 = (s0.x + s1.x) + (s2.x + s3.x), hz1 = (s0.y + s1.y) + (s2.y + s3.y);
            s0 = F2(P3, cr); s1 = F2(P3 + 2304, cr); s2 = F2(P3 + 4608, cr); s3 = F2(P3 + 6912, cr);
            float hr0 = (s0.x + s1.x) + (s2.x + s3.x), hr1 = (s0.y + s1.y) + (s2.y + s3.y);
            s0 = F2(P3, ch); s1 = F2(P3 + 2304, ch); s2 = F2(P3 + 4608, ch); s3 = F2(P3 + 6912, ch);
            float hh0 = (s0.x + s1.x) + (s2.x + s3.x), hh1 = (s0.y + s1.y) + (s2.y + s3.y);
            float4 hv = *(const float4*)&h2d[u * 8 + bo];
            float n0 = gru1s(xz0, hz0, xr0, hr0, xh0, hh0, hv.x);
            float n1 = gru1s(xz1, hz1, xr1, hr1, xh1, hh1, hv.z);
            *(float4*)&h2d[u * 8 + bo] = make_float4(n0, n0, n1, n1);
        } else if (tid < 384) {
            // GRU1 gates, step k+1
            if (k < TT - 1) {
                int t2 = tid - 256;
                int u = t2 & 31, bo = 2 * (t2 >> 5);
                const float* xb = xg1 + ((k + 1) & 1) * 1152;
                int cz = u * 12 + bo, cr = (32 + u) * 12 + bo, ch = (64 + u) * 12 + bo;
                float2 xzv = F2(xb, cz), xrv = F2(xb, cr), xhv = F2(xb, ch);
                float2 p0, p1;
                p0 = F2(P1, cz); p1 = F2(P1 + 1152, cz);
                float hz0 = p0.x + p1.x, hz1 = p0.y + p1.y;
                p0 = F2(P1, cr); p1 = F2(P1 + 1152, cr);
                float hr0 = p0.x + p1.x, hr1 = p0.y + p1.y;
                p0 = F2(P1, ch); p1 = F2(P1 + 1152, ch);
                float hh0 = p0.x + p1.x, hh1 = p0.y + p1.y;
                float4 hv = *(const float4*)&h1d[u * 8 + bo];
                float n0 = gru1s(xzv.x, hz0, xrv.x, hr0, xhv.x, hh0, hv.x);
                float n1 = gru1s(xzv.y, hz1, xrv.y, hr1, xhv.y, hh1, hv.z);
                *(float4*)&h1d[u * 8 + bo] = make_float4(n0, n0, n1, n1);
            }
        }
        if (gi >= 0) {
            if (k < TT - 2) {
                float* xb = xg1 + ((k + 2) & 1) * 1152;
                xb[gj0 * 12 + gb0i] = gv0;
                xb[gj1 * 12 + gb1i] = gv1;
                if (gi < 192) xb[gj2 * 12 + gb2i] = gv2;
            }
            if (((k + 3) & 31) == 0 && (k + 3) < TT && gi < 256) {
                int b = gi >> 5, o = gi & 31;
                tok[b * 32 + o] = tokens[(b0 + b) * TT + (k + 3) + o];
            }
        }
        __syncthreads();
    }

    // ================= Epilogue: GLU + dense + sigmoid =================
    float* ags = (float*)(sbuf + OFF_AGS);   // [8][256]
    float* gws = (float*)(sbuf + OFF_GWS);   // [8][128]
    if (tid < 256) {
        int c = tid;
        float bgv = bg[c];
        u64 acc0 = pk2(bgv, bgv), acc1 = acc0, acc2 = acc0, acc3 = acc0;
        #pragma unroll
        for (int u = 0; u < 64; u++) {
            const float4* hp = (const float4*)&h2d[u * 8];
            float4 v01 = hp[0], v23 = hp[1], v45 = hp[2], v67 = hp[3];
            float wv = __ldg(&wg[u * 256 + c]);
            u64 w = pk2(wv, wv);
            acc0 = ffma2(w, pk2(v01.x, v01.z), acc0);
            acc1 = ffma2(w, pk2(v23.x, v23.z), acc1);
            acc2 = ffma2(w, pk2(v45.x, v45.z), acc2);
            acc3 = ffma2(w, pk2(v67.x, v67.z), acc3);
        }
        float f0, f1;
        upk2(acc0, f0, f1); ags[0 * 256 + c] = f0; ags[1 * 256 + c] = f1;
        upk2(acc1, f0, f1); ags[2 * 256 + c] = f0; ags[3 * 256 + c] = f1;
        upk2(acc2, f0, f1); ags[4 * 256 + c] = f0; ags[5 * 256 + c] = f1;
        upk2(acc3, f0, f1); ags[6 * 256 + c] = f0; ags[7 * 256 + c] = f1;
    }
    __syncthreads();
    for (int i = tid; i < 1024; i += NT) {
        int b = i >> 7, kk = i & 127;
        float g = ags[b * 256 + kk] * sgm(ags[b * 256 + 128 + kk]);
        gws[b * 128 + kk] = g * __ldg(&wd[kk]);
    }
    __syncthreads();
    if (tid < BB) {
        float s = bd[0];
        #pragma unroll
        for (int kk = 0; kk < 128; kk++) s += gws[tid * 128 + kk];
        out[b0 + tid] = sgm(s);
    }
}

// ---------------------------------------------------------------------------
extern "C" void kernel_launch(void* const* d_in, const int* in_sizes, int n_in,
                              void* d_out, int out_size) {
    (void)in_sizes; (void)n_in; (void)out_size;
    const int*   tokens = (const int*)  d_in[0];
    const float* emb    = (const float*)d_in[1];
    const float* kx1    = (const float*)d_in[2];
    const float* kh1    = (const float*)d_in[3];
    const float* b1     = (const float*)d_in[4];
    const float* kx2    = (const float*)d_in[5];
    const float* kh2    = (const float*)d_in[6];
    const float* b2     = (const float*)d_in[7];
    const float* wg     = (const float*)d_in[8];
    const float* bg     = (const float*)d_in[9];
    const float* wd     = (const float*)d_in[10];
    const float* bd     = (const float*)d_in[11];

    static int smem_set = 0;
    if (!smem_set) {
        cudaFuncSetAttribute(rnn_kernel,
                             cudaFuncAttributeMaxDynamicSharedMemorySize, SMEM_SZ);
        smem_set = 1;
    }

    proj_kernel<<<(VSZ + 15) / 16, 256>>>(emb, kx1, b1);
    rnn_kernel<<<BSZ / BB, NT, SMEM_SZ>>>(tokens, kh1, b1, kx2, kh2, b2,
                                          wg, bg, wd, bd, (float*)d_out);
}